// round 1
// baseline (speedup 1.0000x reference)
#include <cuda_runtime.h>
#include <cuda_bf16.h>
#include <math.h>

// Problem constants (fixed by reference)
#define NTOK   1024      // B*S
#define DIM    1024      // hidden
#define NEXP   32        // experts
#define FFN    2048
#define TOPK   4
#define NSLOT  (NTOK*TOPK)   // 4096 assignments

// ---------------- scratch (static device globals; no allocation at runtime) ----
__device__ int   g_count[NEXP];
__device__ int   g_off[NEXP];
__device__ int   g_assign_tok[NEXP * NTOK];
__device__ unsigned char g_assign_k[NEXP * NTOK];
__device__ int   g_slot_token[NSLOT];
__device__ int   g_token_slot[NSLOT];   // [token][k] -> slot
__device__ float g_weight[NSLOT];       // [token][k] -> combine weight
__device__ float g_probs_sum[NEXP];
__device__ float g_H[(size_t)NSLOT * FFN];   // 32 MB
__device__ float g_Y[(size_t)NSLOT * DIM];   // 16 MB

// ---------------- init ---------------------------------------------------------
__global__ void init_kernel() {
    int i = threadIdx.x;
    if (i < NEXP) { g_count[i] = 0; g_probs_sum[i] = 0.0f; }
}

// ---------------- router: logits -> top4 -> softmax -> assignment lists --------
__global__ void router_kernel(const float* __restrict__ x,
                              const float* __restrict__ gw,
                              const float* __restrict__ gb) {
    const int t = blockIdx.x;          // token
    const int tid = threadIdx.x;       // 128 threads
    __shared__ float xs[DIM];
    __shared__ float part[128];
    __shared__ float logits[NEXP];

    for (int i = tid; i < DIM; i += 128) xs[i] = x[(size_t)t * DIM + i];
    __syncthreads();

    const int e = tid & 31;
    const int seg = tid >> 5;          // 4 segments of 256
    float s = 0.0f;
    const int h0 = seg * 256;
    #pragma unroll 4
    for (int h = h0; h < h0 + 256; ++h) s += xs[h] * gw[h * NEXP + e];
    part[tid] = s;
    __syncthreads();

    if (tid < NEXP)
        logits[tid] = part[tid] + part[tid + 32] + part[tid + 64] + part[tid + 96] + gb[tid];
    __syncthreads();

    if (tid == 0) {
        // top-4 (descending, first index on ties -> matches jax.lax.top_k)
        float tv[TOPK]; int ti[TOPK];
        unsigned mask = 0;
        for (int k = 0; k < TOPK; ++k) {
            float best = -3.4e38f; int bi = 0;
            for (int j = 0; j < NEXP; ++j)
                if (!((mask >> j) & 1u) && logits[j] > best) { best = logits[j]; bi = j; }
            mask |= (1u << bi);
            tv[k] = best; ti[k] = bi;
        }
        // softmax over selected
        float m = tv[0], ws = 0.0f, w[TOPK];
        for (int k = 0; k < TOPK; ++k) { w[k] = expf(tv[k] - m); ws += w[k]; }
        for (int k = 0; k < TOPK; ++k) {
            float wk = w[k] / ws;
            g_weight[t * TOPK + k] = wk;
            int ek = ti[k];
            int pos = atomicAdd(&g_count[ek], 1);
            g_assign_tok[ek * NTOK + pos] = t;
            g_assign_k[ek * NTOK + pos] = (unsigned char)k;
        }
        // full softmax probs for aux loss (max over all == tv[0])
        float se = 0.0f, p[NEXP];
        for (int j = 0; j < NEXP; ++j) { p[j] = expf(logits[j] - m); se += p[j]; }
        float inv = 1.0f / se;
        for (int j = 0; j < NEXP; ++j) atomicAdd(&g_probs_sum[j], p[j] * inv);
    }
}

// ---------------- prefix offsets + slot maps ------------------------------------
__global__ void offsets_kernel() {
    __shared__ int soff[NEXP];
    int tid = threadIdx.x;   // 1024 threads
    if (tid == 0) {
        int run = 0;
        for (int e = 0; e < NEXP; ++e) { soff[e] = run; g_off[e] = run; run += g_count[e]; }
    }
    __syncthreads();
    for (int idx = tid; idx < NEXP * NTOK; idx += 1024) {
        int e = idx >> 10, pos = idx & 1023;
        if (pos < g_count[e]) {
            int slot = soff[e] + pos;
            int tok = g_assign_tok[idx];
            g_slot_token[slot] = tok;
            g_token_slot[tok * TOPK + (int)g_assign_k[idx]] = slot;
        }
    }
}

// ---------------- tiled fp32 GEMM helpers ---------------------------------------
__device__ __forceinline__ float gelu_exact(float v) {
    return 0.5f * v * (1.0f + erff(v * 0.70710678118654752f));
}

// GEMM1: H[slot, n] = GELU( sum_k X[tok(slot), k] * W1[e, k, n] + b1[e, n] )
// grid: (FFN/128, 8, NEXP); block: 256
__global__ __launch_bounds__(256) void gemm1_kernel(const float* __restrict__ x,
                                                    const float* __restrict__ w1,
                                                    const float* __restrict__ b1) {
    const int e  = blockIdx.z;
    const int cnt = g_count[e];
    const int m0 = blockIdx.y * 128;
    if (m0 >= cnt) return;
    const int off = g_off[e];
    const int n0 = blockIdx.x * 128;
    const float* __restrict__ B = w1 + (size_t)e * DIM * FFN;

    __shared__ float As[16][132];
    __shared__ float Bs[16][132];

    const int tid = threadIdx.x;
    const int ty = tid >> 4, tx = tid & 15;

    // A loader: 2 threads per row, 8 floats each
    const int arow = tid >> 1;
    const int akc  = (tid & 1) * 8;
    const int r = m0 + arow;
    const float* aptr = (r < cnt) ? (x + (size_t)g_slot_token[off + r] * DIM) : nullptr;
    // B loader: row = tid/16, 8 floats
    const int bk = tid >> 4;
    const int bn = (tid & 15) * 8;

    float acc[8][8];
    #pragma unroll
    for (int i = 0; i < 8; ++i)
        #pragma unroll
        for (int j = 0; j < 8; ++j) acc[i][j] = 0.0f;

    for (int k0 = 0; k0 < DIM; k0 += 16) {
        if (aptr) {
            float4 v0 = *(const float4*)(aptr + k0 + akc);
            float4 v1 = *(const float4*)(aptr + k0 + akc + 4);
            As[akc+0][arow]=v0.x; As[akc+1][arow]=v0.y; As[akc+2][arow]=v0.z; As[akc+3][arow]=v0.w;
            As[akc+4][arow]=v1.x; As[akc+5][arow]=v1.y; As[akc+6][arow]=v1.z; As[akc+7][arow]=v1.w;
        } else {
            #pragma unroll
            for (int i = 0; i < 8; ++i) As[akc+i][arow] = 0.0f;
        }
        const float* bp = B + (size_t)(k0 + bk) * FFN + n0 + bn;
        float4 u0 = *(const float4*)bp;
        float4 u1 = *(const float4*)(bp + 4);
        *(float4*)&Bs[bk][bn]   = u0;
        *(float4*)&Bs[bk][bn+4] = u1;
        __syncthreads();
        #pragma unroll
        for (int kk = 0; kk < 16; ++kk) {
            float4 a0 = *(const float4*)&As[kk][ty*8];
            float4 a1 = *(const float4*)&As[kk][ty*8+4];
            float4 c0 = *(const float4*)&Bs[kk][tx*8];
            float4 c1 = *(const float4*)&Bs[kk][tx*8+4];
            float a[8] = {a0.x,a0.y,a0.z,a0.w,a1.x,a1.y,a1.z,a1.w};
            float b[8] = {c0.x,c0.y,c0.z,c0.w,c1.x,c1.y,c1.z,c1.w};
            #pragma unroll
            for (int i = 0; i < 8; ++i)
                #pragma unroll
                for (int j = 0; j < 8; ++j) acc[i][j] = fmaf(a[i], b[j], acc[i][j]);
        }
        __syncthreads();
    }

    const float* bb = b1 + (size_t)e * FFN + n0 + tx * 8;
    float bias[8];
    #pragma unroll
    for (int j = 0; j < 8; ++j) bias[j] = bb[j];
    #pragma unroll
    for (int i = 0; i < 8; ++i) {
        int rr = m0 + ty * 8 + i;
        if (rr < cnt) {
            float* hrow = g_H + (size_t)(off + rr) * FFN + n0 + tx * 8;
            #pragma unroll
            for (int j = 0; j < 8; ++j) hrow[j] = gelu_exact(acc[i][j] + bias[j]);
        }
    }
}

// GEMM2: Y[slot, n] = sum_k H[slot, k] * W2[e, k, n] + b2[e, n]
// grid: (DIM/128, 8, NEXP); block: 256
__global__ __launch_bounds__(256) void gemm2_kernel(const float* __restrict__ w2,
                                                    const float* __restrict__ b2) {
    const int e  = blockIdx.z;
    const int cnt = g_count[e];
    const int m0 = blockIdx.y * 128;
    if (m0 >= cnt) return;
    const int off = g_off[e];
    const int n0 = blockIdx.x * 128;
    const float* __restrict__ B = w2 + (size_t)e * FFN * DIM;

    __shared__ float As[16][132];
    __shared__ float Bs[16][132];

    const int tid = threadIdx.x;
    const int ty = tid >> 4, tx = tid & 15;
    const int arow = tid >> 1;
    const int akc  = (tid & 1) * 8;
    const int r = m0 + arow;
    const float* aptr = (r < cnt) ? (g_H + (size_t)(off + r) * FFN) : nullptr;
    const int bk = tid >> 4;
    const int bn = (tid & 15) * 8;

    float acc[8][8];
    #pragma unroll
    for (int i = 0; i < 8; ++i)
        #pragma unroll
        for (int j = 0; j < 8; ++j) acc[i][j] = 0.0f;

    for (int k0 = 0; k0 < FFN; k0 += 16) {
        if (aptr) {
            float4 v0 = *(const float4*)(aptr + k0 + akc);
            float4 v1 = *(const float4*)(aptr + k0 + akc + 4);
            As[akc+0][arow]=v0.x; As[akc+1][arow]=v0.y; As[akc+2][arow]=v0.z; As[akc+3][arow]=v0.w;
            As[akc+4][arow]=v1.x; As[akc+5][arow]=v1.y; As[akc+6][arow]=v1.z; As[akc+7][arow]=v1.w;
        } else {
            #pragma unroll
            for (int i = 0; i < 8; ++i) As[akc+i][arow] = 0.0f;
        }
        const float* bp = B + (size_t)(k0 + bk) * DIM + n0 + bn;
        float4 u0 = *(const float4*)bp;
        float4 u1 = *(const float4*)(bp + 4);
        *(float4*)&Bs[bk][bn]   = u0;
        *(float4*)&Bs[bk][bn+4] = u1;
        __syncthreads();
        #pragma unroll
        for (int kk = 0; kk < 16; ++kk) {
            float4 a0 = *(const float4*)&As[kk][ty*8];
            float4 a1 = *(const float4*)&As[kk][ty*8+4];
            float4 c0 = *(const float4*)&Bs[kk][tx*8];
            float4 c1 = *(const float4*)&Bs[kk][tx*8+4];
            float a[8] = {a0.x,a0.y,a0.z,a0.w,a1.x,a1.y,a1.z,a1.w};
            float b[8] = {c0.x,c0.y,c0.z,c0.w,c1.x,c1.y,c1.z,c1.w};
            #pragma unroll
            for (int i = 0; i < 8; ++i)
                #pragma unroll
                for (int j = 0; j < 8; ++j) acc[i][j] = fmaf(a[i], b[j], acc[i][j]);
        }
        __syncthreads();
    }

    const float* bb = b2 + (size_t)e * DIM + n0 + tx * 8;
    float bias[8];
    #pragma unroll
    for (int j = 0; j < 8; ++j) bias[j] = bb[j];
    #pragma unroll
    for (int i = 0; i < 8; ++i) {
        int rr = m0 + ty * 8 + i;
        if (rr < cnt) {
            float* yrow = g_Y + (size_t)(off + rr) * DIM + n0 + tx * 8;
            #pragma unroll
            for (int j = 0; j < 8; ++j) yrow[j] = acc[i][j] + bias[j];
        }
    }
}

// ---------------- deterministic combine: out[t] = sum_k w_k * Y[slot(t,k)] ------
__global__ void combine_kernel(float* __restrict__ out) {
    const int t = blockIdx.x;
    const int tid = threadIdx.x;  // 256
    __shared__ float w[TOPK];
    __shared__ int   s[TOPK];
    if (tid < TOPK) { w[tid] = g_weight[t * TOPK + tid]; s[tid] = g_token_slot[t * TOPK + tid]; }
    __syncthreads();
    const float* y0 = g_Y + (size_t)s[0] * DIM;
    const float* y1 = g_Y + (size_t)s[1] * DIM;
    const float* y2 = g_Y + (size_t)s[2] * DIM;
    const float* y3 = g_Y + (size_t)s[3] * DIM;
    float* o = out + (size_t)t * DIM;
    for (int h = tid; h < DIM; h += 256)
        o[h] = w[0]*y0[h] + w[1]*y1[h] + w[2]*y2[h] + w[3]*y3[h];
}

// ---------------- aux scalar ------------------------------------------------------
__global__ void aux_kernel(const float* __restrict__ load_ema, float* __restrict__ aux_out) {
    // single warp
    int e = threadIdx.x;  // 32 threads
    float frac = ((float)g_count[e] / (float)NTOK) / (float)TOPK;
    float pm   = g_probs_sum[e] / (float)NTOK;
    float contrib = frac * pm;
    float ema = load_ema[e];
    // warp reductions
    float csum = contrib, esum = ema;
    #pragma unroll
    for (int o = 16; o > 0; o >>= 1) {
        csum += __shfl_xor_sync(0xffffffff, csum, o);
        esum += __shfl_xor_sync(0xffffffff, esum, o);
    }
    float lp = ema / (esum + 1e-8f);
    float ent_term = -lp * logf(lp + 1e-8f);
    float entropy = ent_term;
    #pragma unroll
    for (int o = 16; o > 0; o >>= 1)
        entropy += __shfl_xor_sync(0xffffffff, entropy, o);
    if (e == 0) {
        float base_aux = (float)NEXP * csum;
        float reg = logf((float)NEXP) - entropy;
        aux_out[0] = base_aux + 0.001f * reg;
    }
}

// ---------------- launch ----------------------------------------------------------
extern "C" void kernel_launch(void* const* d_in, const int* in_sizes, int n_in,
                              void* d_out, int out_size) {
    const float* x    = (const float*)d_in[0];
    const float* gw   = (const float*)d_in[1];
    const float* gb   = (const float*)d_in[2];
    const float* w1   = (const float*)d_in[3];
    const float* b1   = (const float*)d_in[4];
    const float* w2   = (const float*)d_in[5];
    const float* b2   = (const float*)d_in[6];
    const float* ema  = (const float*)d_in[7];
    float* out = (float*)d_out;

    init_kernel<<<1, 64>>>();
    router_kernel<<<NTOK, 128>>>(x, gw, gb);
    offsets_kernel<<<1, 1024>>>();
    gemm1_kernel<<<dim3(FFN/128, NTOK/128, NEXP), 256>>>(x, w1, b1);
    gemm2_kernel<<<dim3(DIM/128, NTOK/128, NEXP), 256>>>(w2, b2);
    combine_kernel<<<NTOK, 256>>>(out);
    if (out_size > NTOK * DIM) {
        aux_kernel<<<1, 32>>>(ema, out + (size_t)NTOK * DIM);
    }
}

// round 13
// speedup vs baseline: 1.8240x; 1.8240x over previous
#include <cuda_runtime.h>
#include <cuda_bf16.h>
#include <cstdint>
#include <math.h>

// ---------------- problem constants ----------------
#define NTOK   1024
#define DIM    1024
#define NEXP   32
#define FFN    2048
#define TOPK   4
#define NSLOT  (NTOK*TOPK)

// ---------------- tile config ----------------
#define TM 128
#define TN 128
#define KC 32
#define A_STRIDE 40      // bf16 per A smem row (32 data + 8 pad)
#define BP_STRIDE 136    // uint32 per packed-B smem row (128 data + 8 pad)

// ---------------- scratch (device globals; referenced ONLY in device code) ----
__device__ int   g_count[NEXP];
__device__ int   g_off[NEXP];
__device__ int   g_assign_tok[NEXP * NTOK];
__device__ unsigned char g_assign_k[NEXP * NTOK];
__device__ int   g_slot_token[NSLOT];
__device__ int   g_token_slot[NSLOT];
__device__ float g_weight[NSLOT];
__device__ float g_probs_sum[NEXP];
__device__ float g_H[(size_t)NSLOT * FFN];   // 32 MB
__device__ float g_Y[(size_t)NSLOT * DIM];   // 16 MB

// ---------------- init ----------------
__global__ void init_kernel() {
    int i = threadIdx.x;
    if (i < NEXP) { g_count[i] = 0; g_probs_sum[i] = 0.0f; }
}

// ---------------- router ----------------
__global__ void router_kernel(const float* __restrict__ x,
                              const float* __restrict__ gw,
                              const float* __restrict__ gb) {
    const int t = blockIdx.x;
    const int tid = threadIdx.x;       // 128
    __shared__ float xs[DIM];
    __shared__ float part[128];
    __shared__ float logits[NEXP];

    for (int i = tid; i < DIM; i += 128) xs[i] = x[(size_t)t * DIM + i];
    __syncthreads();

    const int e = tid & 31;
    const int seg = tid >> 5;
    float s = 0.0f;
    const int h0 = seg * 256;
    #pragma unroll 4
    for (int h = h0; h < h0 + 256; ++h) s += xs[h] * gw[h * NEXP + e];
    part[tid] = s;
    __syncthreads();

    if (tid < NEXP)
        logits[tid] = part[tid] + part[tid + 32] + part[tid + 64] + part[tid + 96] + gb[tid];
    __syncthreads();

    if (tid == 0) {
        float tv[TOPK]; int ti[TOPK];
        unsigned mask = 0;
        for (int k = 0; k < TOPK; ++k) {
            float best = -3.4e38f; int bi = 0;
            for (int j = 0; j < NEXP; ++j)
                if (!((mask >> j) & 1u) && logits[j] > best) { best = logits[j]; bi = j; }
            mask |= (1u << bi);
            tv[k] = best; ti[k] = bi;
        }
        float m = tv[0], ws = 0.0f, w[TOPK];
        for (int k = 0; k < TOPK; ++k) { w[k] = expf(tv[k] - m); ws += w[k]; }
        for (int k = 0; k < TOPK; ++k) {
            float wk = w[k] / ws;
            g_weight[t * TOPK + k] = wk;
            int ek = ti[k];
            int pos = atomicAdd(&g_count[ek], 1);
            g_assign_tok[ek * NTOK + pos] = t;
            g_assign_k[ek * NTOK + pos] = (unsigned char)k;
        }
        float se = 0.0f, p[NEXP];
        for (int j = 0; j < NEXP; ++j) { p[j] = expf(logits[j] - m); se += p[j]; }
        float inv = 1.0f / se;
        for (int j = 0; j < NEXP; ++j) atomicAdd(&g_probs_sum[j], p[j] * inv);
    }
}

// ---------------- offsets ----------------
__global__ void offsets_kernel() {
    __shared__ int soff[NEXP];
    int tid = threadIdx.x;
    if (tid == 0) {
        int run = 0;
        for (int e = 0; e < NEXP; ++e) { soff[e] = run; g_off[e] = run; run += g_count[e]; }
    }
    __syncthreads();
    for (int idx = tid; idx < NEXP * NTOK; idx += 1024) {
        int e = idx >> 10, pos = idx & 1023;
        if (pos < g_count[e]) {
            int slot = soff[e] + pos;
            int tok = g_assign_tok[idx];
            g_slot_token[slot] = tok;
            g_token_slot[tok * TOPK + (int)g_assign_k[idx]] = slot;
        }
    }
}

__device__ __forceinline__ float gelu_exact(float v) {
    return 0.5f * v * (1.0f + erff(v * 0.70710678118654752f));
}

// ---------------- mma helper ----------------
__device__ __forceinline__ void mma_bf16(float* d, const uint32_t* a, uint32_t b0, uint32_t b1) {
    asm volatile(
        "mma.sync.aligned.m16n8k16.row.col.f32.bf16.bf16.f32 "
        "{%0,%1,%2,%3}, {%4,%5,%6,%7}, {%8,%9}, {%0,%1,%2,%3};"
        : "+f"(d[0]), "+f"(d[1]), "+f"(d[2]), "+f"(d[3])
        : "r"(a[0]), "r"(a[1]), "r"(a[2]), "r"(a[3]), "r"(b0), "r"(b1));
}

__device__ __forceinline__ uint32_t pack_bf16(__nv_bfloat16 lo, __nv_bfloat16 hi) {
    uint16_t l = __nv_bfloat16_raw(lo).x;
    uint16_t h = __nv_bfloat16_raw(hi).x;
    return (uint32_t)l | ((uint32_t)h << 16);
}

__device__ __forceinline__ void split_bf16(float v, __nv_bfloat16& h, __nv_bfloat16& l) {
    h = __float2bfloat16(v);
    l = __float2bfloat16(v - __bfloat162float(h));
}

// ---------------- grouped GEMM: manual-fragment bf16-split HMMA ----------------
// SRC_H: A rows come from g_H (by slot); else from xparam (gathered by token).
// DST_H: output to g_H; else to g_Y.
template<int KTOT, int NTOT, bool DOGELU, bool GATHER, bool SRC_H, bool DST_H>
__global__ __launch_bounds__(256)
void moe_gemm(const float* __restrict__ xparam,
              const float* __restrict__ W,
              const float* __restrict__ bias) {
    const int e   = blockIdx.z;
    const int cnt = g_count[e];
    const int m0  = blockIdx.y * TM;
    if (m0 >= cnt) return;
    const int off = g_off[e];
    const int n0  = blockIdx.x * TN;
    const float* __restrict__ Wp = W + (size_t)e * KTOT * NTOT;
    const float* __restrict__ Abase = SRC_H ? (const float*)g_H : xparam;
    float* __restrict__ Out = DST_H ? (float*)g_H : (float*)g_Y;

    // A: bf16 [m][k], hi & lo planes
    __shared__ __nv_bfloat16 Ah[TM][A_STRIDE];
    __shared__ __nv_bfloat16 Al[TM][A_STRIDE];
    // B: packed k-pairs: word [kp][n] = (B[2kp][n] in low half, B[2kp+1][n] in high half)
    __shared__ uint32_t Bh[KC/2][BP_STRIDE];
    __shared__ uint32_t Bl[KC/2][BP_STRIDE];

    const int tid = threadIdx.x;
    const int wid = tid >> 5, lid = tid & 31;
    const int wm  = wid & 3;          // m offset wm*32
    const int wn  = wid >> 2;         // n offset wn*64
    const int g   = lid >> 2;         // groupID 0..7
    const int tig = lid & 3;          // thread-in-group 0..3

    // A loader: 2 threads per row, 16 k each
    const int arow = tid >> 1;
    const int akc0 = (tid & 1) * 16;
    const float* aptr = nullptr;
    if (m0 + arow < cnt) {
        if (GATHER) aptr = Abase + (size_t)g_slot_token[off + m0 + arow] * KTOT;
        else        aptr = Abase + (size_t)(off + m0 + arow) * KTOT;
    }
    // B loader: thread handles k-pair row bkp, 8 n columns
    const int bkp = tid >> 4;         // 0..15
    const int bn8 = (tid & 15) * 8;   // 0..120

    float acc[2][8][4];
    #pragma unroll
    for (int i = 0; i < 2; ++i)
        #pragma unroll
        for (int j = 0; j < 8; ++j)
            #pragma unroll
            for (int q = 0; q < 4; ++q) acc[i][j][q] = 0.0f;

    for (int k0 = 0; k0 < KTOT; k0 += KC) {
        __syncthreads();
        // ---- stage A chunk (hi/lo split) ----
        {
            float v[16];
            if (aptr) {
                #pragma unroll
                for (int q = 0; q < 4; ++q) {
                    float4 f = *(const float4*)(aptr + k0 + akc0 + q * 4);
                    v[q*4+0]=f.x; v[q*4+1]=f.y; v[q*4+2]=f.z; v[q*4+3]=f.w;
                }
            } else {
                #pragma unroll
                for (int q = 0; q < 16; ++q) v[q] = 0.0f;
            }
            union { uint4 u[2]; __nv_bfloat16 h[16]; } hi, lo;
            #pragma unroll
            for (int q = 0; q < 16; ++q) split_bf16(v[q], hi.h[q], lo.h[q]);
            *(uint4*)&Ah[arow][akc0]     = hi.u[0];
            *(uint4*)&Ah[arow][akc0 + 8] = hi.u[1];
            *(uint4*)&Al[arow][akc0]     = lo.u[0];
            *(uint4*)&Al[arow][akc0 + 8] = lo.u[1];
        }
        // ---- stage B chunk: read two adjacent k rows, pack k-pairs ----
        {
            const float* r0 = Wp + (size_t)(k0 + 2*bkp    ) * NTOT + n0 + bn8;
            const float* r1 = Wp + (size_t)(k0 + 2*bkp + 1) * NTOT + n0 + bn8;
            float4 a0 = *(const float4*)(r0);
            float4 a1 = *(const float4*)(r0 + 4);
            float4 c0 = *(const float4*)(r1);
            float4 c1 = *(const float4*)(r1 + 4);
            float e0[8] = {a0.x,a0.y,a0.z,a0.w,a1.x,a1.y,a1.z,a1.w};
            float e1[8] = {c0.x,c0.y,c0.z,c0.w,c1.x,c1.y,c1.z,c1.w};
            uint32_t wh[8], wl[8];
            #pragma unroll
            for (int j = 0; j < 8; ++j) {
                __nv_bfloat16 h0, l0, h1, l1;
                split_bf16(e0[j], h0, l0);
                split_bf16(e1[j], h1, l1);
                wh[j] = pack_bf16(h0, h1);   // low half = even-k element
                wl[j] = pack_bf16(l0, l1);
            }
            *(uint4*)&Bh[bkp][bn8]     = make_uint4(wh[0],wh[1],wh[2],wh[3]);
            *(uint4*)&Bh[bkp][bn8 + 4] = make_uint4(wh[4],wh[5],wh[6],wh[7]);
            *(uint4*)&Bl[bkp][bn8]     = make_uint4(wl[0],wl[1],wl[2],wl[3]);
            *(uint4*)&Bl[bkp][bn8 + 4] = make_uint4(wl[4],wl[5],wl[6],wl[7]);
        }
        __syncthreads();

        // ---- MMAs: 2 k-steps of 16 ----
        #pragma unroll
        for (int ks = 0; ks < 2; ++ks) {
            // A frags (PTX m16n8k16.row layout):
            // r0=(m=g, k=2tig,2tig+1) r1=(m=g+8, same) r2=(m=g, k+8) r3=(m=g+8, k+8)
            uint32_t ah[2][4], al[2][4];
            #pragma unroll
            for (int mf = 0; mf < 2; ++mf) {
                const int mb = wm * 32 + mf * 16;
                const int kc = ks * 16 + 2 * tig;
                ah[mf][0] = *(const uint32_t*)&Ah[mb + g    ][kc    ];
                ah[mf][1] = *(const uint32_t*)&Ah[mb + g + 8][kc    ];
                ah[mf][2] = *(const uint32_t*)&Ah[mb + g    ][kc + 8];
                ah[mf][3] = *(const uint32_t*)&Ah[mb + g + 8][kc + 8];
                al[mf][0] = *(const uint32_t*)&Al[mb + g    ][kc    ];
                al[mf][1] = *(const uint32_t*)&Al[mb + g + 8][kc    ];
                al[mf][2] = *(const uint32_t*)&Al[mb + g    ][kc + 8];
                al[mf][3] = *(const uint32_t*)&Al[mb + g + 8][kc + 8];
            }
            #pragma unroll
            for (int ng = 0; ng < 8; ++ng) {
                // B frags (col layout): b0=(k=2tig..,n=g), b1=(k=2tig+8..,n=g)
                const int nn = wn * 64 + ng * 8 + g;
                const uint32_t bh0 = Bh[ks*8 + tig    ][nn];
                const uint32_t bh1 = Bh[ks*8 + tig + 4][nn];
                const uint32_t bl0 = Bl[ks*8 + tig    ][nn];
                const uint32_t bl1 = Bl[ks*8 + tig + 4][nn];
                #pragma unroll
                for (int mf = 0; mf < 2; ++mf) {
                    mma_bf16(acc[mf][ng], ah[mf], bh0, bh1);   // hi*hi
                    mma_bf16(acc[mf][ng], al[mf], bh0, bh1);   // lo*hi
                    mma_bf16(acc[mf][ng], ah[mf], bl0, bl1);   // hi*lo
                }
            }
        }
    }

    // ---- epilogue: c0,c1 at (row g, cols 2tig..); c2,c3 at (row g+8) ----
    #pragma unroll
    for (int mf = 0; mf < 2; ++mf) {
        const int rbase = m0 + wm * 32 + mf * 16;
        #pragma unroll
        for (int half = 0; half < 2; ++half) {
            const int r = rbase + g + half * 8;
            if (r < cnt) {
                float* orow = Out + (size_t)(off + r) * NTOT + n0;
                const float* brow = bias + (size_t)e * NTOT + n0;
                #pragma unroll
                for (int ng = 0; ng < 8; ++ng) {
                    const int c = wn * 64 + ng * 8 + tig * 2;
                    float v0 = acc[mf][ng][half * 2 + 0] + brow[c];
                    float v1 = acc[mf][ng][half * 2 + 1] + brow[c + 1];
                    if (DOGELU) { v0 = gelu_exact(v0); v1 = gelu_exact(v1); }
                    orow[c]     = v0;
                    orow[c + 1] = v1;
                }
            }
        }
    }
}

// ---------------- combine ----------------
__global__ void combine_kernel(float* __restrict__ out) {
    const int t = blockIdx.x;
    const int tid = threadIdx.x;
    __shared__ float w[TOPK];
    __shared__ int   s[TOPK];
    if (tid < TOPK) { w[tid] = g_weight[t * TOPK + tid]; s[tid] = g_token_slot[t * TOPK + tid]; }
    __syncthreads();
    const float* y0 = g_Y + (size_t)s[0] * DIM;
    const float* y1 = g_Y + (size_t)s[1] * DIM;
    const float* y2 = g_Y + (size_t)s[2] * DIM;
    const float* y3 = g_Y + (size_t)s[3] * DIM;
    float* o = out + (size_t)t * DIM;
    for (int h = tid; h < DIM; h += 256)
        o[h] = w[0]*y0[h] + w[1]*y1[h] + w[2]*y2[h] + w[3]*y3[h];
}

// ---------------- aux scalar ----------------
__global__ void aux_kernel(const float* __restrict__ load_ema, float* __restrict__ aux_out) {
    int e = threadIdx.x;  // 32
    float frac = ((float)g_count[e] / (float)NTOK) / (float)TOPK;
    float pm   = g_probs_sum[e] / (float)NTOK;
    float contrib = frac * pm;
    float ema = load_ema[e];
    float csum = contrib, esum = ema;
    #pragma unroll
    for (int o = 16; o > 0; o >>= 1) {
        csum += __shfl_xor_sync(0xffffffff, csum, o);
        esum += __shfl_xor_sync(0xffffffff, esum, o);
    }
    float lp = ema / (esum + 1e-8f);
    float entropy = -lp * logf(lp + 1e-8f);
    #pragma unroll
    for (int o = 16; o > 0; o >>= 1)
        entropy += __shfl_xor_sync(0xffffffff, entropy, o);
    if (e == 0) {
        float base_aux = (float)NEXP * csum;
        float reg = logf((float)NEXP) - entropy;
        aux_out[0] = base_aux + 0.001f * reg;
    }
}

// ---------------- launch ----------------
extern "C" void kernel_launch(void* const* d_in, const int* in_sizes, int n_in,
                              void* d_out, int out_size) {
    const float* x   = (const float*)d_in[0];
    const float* gw  = (const float*)d_in[1];
    const float* gb  = (const float*)d_in[2];
    const float* w1  = (const float*)d_in[3];
    const float* b1  = (const float*)d_in[4];
    const float* w2  = (const float*)d_in[5];
    const float* b2  = (const float*)d_in[6];
    const float* ema = (const float*)d_in[7];
    float* out = (float*)d_out;

    init_kernel<<<1, 64>>>();
    router_kernel<<<NTOK, 128>>>(x, gw, gb);
    offsets_kernel<<<1, 1024>>>();

    // GEMM1: g_H = GELU(X_gathered @ W1 + b1)
    moe_gemm<DIM, FFN, true, true, false, true>
        <<<dim3(FFN / TN, NTOK / TM, NEXP), 256>>>(x, w1, b1);
    // GEMM2: g_Y = g_H @ W2 + b2
    moe_gemm<FFN, DIM, false, false, true, false>
        <<<dim3(DIM / TN, NTOK / TM, NEXP), 256>>>(x, w2, b2);

    combine_kernel<<<NTOK, 256>>>(out);
    if (out_size > NTOK * DIM) {
        aux_kernel<<<1, 32>>>(ema, out + (size_t)NTOK * DIM);
    }
}

// round 16
// speedup vs baseline: 2.2141x; 1.2139x over previous
#include <cuda_runtime.h>
#include <cuda_bf16.h>
#include <cstdint>
#include <math.h>

// ---------------- problem constants ----------------
#define NTOK   1024
#define DIM    1024
#define NEXP   32
#define FFN    2048
#define TOPK   4
#define NSLOT  (NTOK*TOPK)

// ---------------- tile config ----------------
#define TM 128
#define TN 128
#define KC 32
#define A_STRIDE 40      // bf16 per A smem row (32 data + 8 pad)
#define BP_STRIDE 136    // uint32 per packed-B smem row (128 data + 8 pad)

// ---------------- scratch (device globals; referenced ONLY in device code) ----
__device__ int   g_count[NEXP];
__device__ int   g_off[NEXP];
__device__ int   g_assign_tok[NEXP * NTOK];
__device__ unsigned char g_assign_k[NEXP * NTOK];
__device__ int   g_slot_token[NSLOT];
__device__ int   g_token_slot[NSLOT];
__device__ float g_weight[NSLOT];
__device__ float g_probs_sum[NEXP];
__device__ float g_H[(size_t)NSLOT * FFN];   // 32 MB
__device__ float g_Y[(size_t)NSLOT * DIM];   // 16 MB

// ---------------- init ----------------
__global__ void init_kernel() {
    int i = threadIdx.x;
    if (i < NEXP) { g_count[i] = 0; g_probs_sum[i] = 0.0f; }
}

// ---------------- router ----------------
__global__ void router_kernel(const float* __restrict__ x,
                              const float* __restrict__ gw,
                              const float* __restrict__ gb) {
    const int t = blockIdx.x;
    const int tid = threadIdx.x;       // 128
    __shared__ float xs[DIM];
    __shared__ float part[128];
    __shared__ float logits[NEXP];

    for (int i = tid; i < DIM; i += 128) xs[i] = x[(size_t)t * DIM + i];
    __syncthreads();

    const int e = tid & 31;
    const int seg = tid >> 5;
    float s = 0.0f;
    const int h0 = seg * 256;
    #pragma unroll 4
    for (int h = h0; h < h0 + 256; ++h) s += xs[h] * gw[h * NEXP + e];
    part[tid] = s;
    __syncthreads();

    if (tid < NEXP)
        logits[tid] = part[tid] + part[tid + 32] + part[tid + 64] + part[tid + 96] + gb[tid];
    __syncthreads();

    if (tid == 0) {
        float tv[TOPK]; int ti[TOPK];
        unsigned mask = 0;
        for (int k = 0; k < TOPK; ++k) {
            float best = -3.4e38f; int bi = 0;
            for (int j = 0; j < NEXP; ++j)
                if (!((mask >> j) & 1u) && logits[j] > best) { best = logits[j]; bi = j; }
            mask |= (1u << bi);
            tv[k] = best; ti[k] = bi;
        }
        float m = tv[0], ws = 0.0f, w[TOPK];
        for (int k = 0; k < TOPK; ++k) { w[k] = expf(tv[k] - m); ws += w[k]; }
        for (int k = 0; k < TOPK; ++k) {
            float wk = w[k] / ws;
            g_weight[t * TOPK + k] = wk;
            int ek = ti[k];
            int pos = atomicAdd(&g_count[ek], 1);
            g_assign_tok[ek * NTOK + pos] = t;
            g_assign_k[ek * NTOK + pos] = (unsigned char)k;
        }
        float se = 0.0f, p[NEXP];
        for (int j = 0; j < NEXP; ++j) { p[j] = expf(logits[j] - m); se += p[j]; }
        float inv = 1.0f / se;
        for (int j = 0; j < NEXP; ++j) atomicAdd(&g_probs_sum[j], p[j] * inv);
    }
}

// ---------------- offsets ----------------
__global__ void offsets_kernel() {
    __shared__ int soff[NEXP];
    int tid = threadIdx.x;
    if (tid == 0) {
        int run = 0;
        for (int e = 0; e < NEXP; ++e) { soff[e] = run; g_off[e] = run; run += g_count[e]; }
    }
    __syncthreads();
    for (int idx = tid; idx < NEXP * NTOK; idx += 1024) {
        int e = idx >> 10, pos = idx & 1023;
        if (pos < g_count[e]) {
            int slot = soff[e] + pos;
            int tok = g_assign_tok[idx];
            g_slot_token[slot] = tok;
            g_token_slot[tok * TOPK + (int)g_assign_k[idx]] = slot;
        }
    }
}

__device__ __forceinline__ float gelu_exact(float v) {
    return 0.5f * v * (1.0f + erff(v * 0.70710678118654752f));
}

// ---------------- mma helper ----------------
__device__ __forceinline__ void mma_bf16(float* d, const uint32_t* a, uint32_t b0, uint32_t b1) {
    asm volatile(
        "mma.sync.aligned.m16n8k16.row.col.f32.bf16.bf16.f32 "
        "{%0,%1,%2,%3}, {%4,%5,%6,%7}, {%8,%9}, {%0,%1,%2,%3};"
        : "+f"(d[0]), "+f"(d[1]), "+f"(d[2]), "+f"(d[3])
        : "r"(a[0]), "r"(a[1]), "r"(a[2]), "r"(a[3]), "r"(b0), "r"(b1));
}

__device__ __forceinline__ uint32_t pack_bf16(__nv_bfloat16 lo, __nv_bfloat16 hi) {
    uint16_t l = __nv_bfloat16_raw(lo).x;
    uint16_t h = __nv_bfloat16_raw(hi).x;
    return (uint32_t)l | ((uint32_t)h << 16);
}

__device__ __forceinline__ void split_bf16(float v, __nv_bfloat16& h, __nv_bfloat16& l) {
    h = __float2bfloat16(v);
    l = __float2bfloat16(v - __bfloat162float(h));
}

// ---------------- grouped GEMM: manual-fragment bf16-split HMMA ----------------
// SRC_H: A rows come from g_H (by slot); else from xparam (gathered by token).
// DST_H: output to g_H; else to g_Y.
template<int KTOT, int NTOT, bool DOGELU, bool GATHER, bool SRC_H, bool DST_H>
__global__ __launch_bounds__(256, 2)
void moe_gemm(const float* __restrict__ xparam,
              const float* __restrict__ W,
              const float* __restrict__ bias) {
    const int e   = blockIdx.z;
    const int cnt = g_count[e];
    const int m0  = blockIdx.y * TM;
    if (m0 >= cnt) return;
    const int off = g_off[e];
    const int n0  = blockIdx.x * TN;
    const float* __restrict__ Wp = W + (size_t)e * KTOT * NTOT;
    const float* __restrict__ Abase = SRC_H ? (const float*)g_H : xparam;
    float* __restrict__ Out = DST_H ? (float*)g_H : (float*)g_Y;

    // A: bf16 [m][k], hi & lo planes
    __shared__ __nv_bfloat16 Ah[TM][A_STRIDE];
    __shared__ __nv_bfloat16 Al[TM][A_STRIDE];
    // B: packed k-pairs: word [kp][n] = (B[2kp][n] in low half, B[2kp+1][n] in high half)
    __shared__ uint32_t Bh[KC/2][BP_STRIDE];
    __shared__ uint32_t Bl[KC/2][BP_STRIDE];

    const int tid = threadIdx.x;
    const int wid = tid >> 5, lid = tid & 31;
    const int wm  = wid & 3;          // m offset wm*32
    const int wn  = wid >> 2;         // n offset wn*64
    const int g   = lid >> 2;         // groupID 0..7
    const int tig = lid & 3;          // thread-in-group 0..3

    // A loader: 2 threads per row, 16 k each
    const int arow = tid >> 1;
    const int akc0 = (tid & 1) * 16;
    const float* aptr = nullptr;
    if (m0 + arow < cnt) {
        if (GATHER) aptr = Abase + (size_t)g_slot_token[off + m0 + arow] * KTOT;
        else        aptr = Abase + (size_t)(off + m0 + arow) * KTOT;
    }
    // B loader: thread handles k-pair row bkp, 8 n columns
    const int bkp = tid >> 4;         // 0..15
    const int bn8 = (tid & 15) * 8;   // 0..120

    float acc[2][8][4];
    #pragma unroll
    for (int i = 0; i < 2; ++i)
        #pragma unroll
        for (int j = 0; j < 8; ++j)
            #pragma unroll
            for (int q = 0; q < 4; ++q) acc[i][j][q] = 0.0f;

    for (int k0 = 0; k0 < KTOT; k0 += KC) {
        __syncthreads();
        // ---- stage A chunk (hi/lo split) ----
        {
            float v[16];
            if (aptr) {
                #pragma unroll
                for (int q = 0; q < 4; ++q) {
                    float4 f = *(const float4*)(aptr + k0 + akc0 + q * 4);
                    v[q*4+0]=f.x; v[q*4+1]=f.y; v[q*4+2]=f.z; v[q*4+3]=f.w;
                }
            } else {
                #pragma unroll
                for (int q = 0; q < 16; ++q) v[q] = 0.0f;
            }
            union { uint4 u[2]; __nv_bfloat16 h[16]; } hi, lo;
            #pragma unroll
            for (int q = 0; q < 16; ++q) split_bf16(v[q], hi.h[q], lo.h[q]);
            *(uint4*)&Ah[arow][akc0]     = hi.u[0];
            *(uint4*)&Ah[arow][akc0 + 8] = hi.u[1];
            *(uint4*)&Al[arow][akc0]     = lo.u[0];
            *(uint4*)&Al[arow][akc0 + 8] = lo.u[1];
        }
        // ---- stage B chunk: read two adjacent k rows, pack k-pairs ----
        {
            const float* r0 = Wp + (size_t)(k0 + 2*bkp    ) * NTOT + n0 + bn8;
            const float* r1 = Wp + (size_t)(k0 + 2*bkp + 1) * NTOT + n0 + bn8;
            float4 a0 = *(const float4*)(r0);
            float4 a1 = *(const float4*)(r0 + 4);
            float4 c0 = *(const float4*)(r1);
            float4 c1 = *(const float4*)(r1 + 4);
            float e0[8] = {a0.x,a0.y,a0.z,a0.w,a1.x,a1.y,a1.z,a1.w};
            float e1[8] = {c0.x,c0.y,c0.z,c0.w,c1.x,c1.y,c1.z,c1.w};
            uint32_t wh[8], wl[8];
            #pragma unroll
            for (int j = 0; j < 8; ++j) {
                __nv_bfloat16 h0, l0, h1, l1;
                split_bf16(e0[j], h0, l0);
                split_bf16(e1[j], h1, l1);
                wh[j] = pack_bf16(h0, h1);   // low half = even-k element
                wl[j] = pack_bf16(l0, l1);
            }
            *(uint4*)&Bh[bkp][bn8]     = make_uint4(wh[0],wh[1],wh[2],wh[3]);
            *(uint4*)&Bh[bkp][bn8 + 4] = make_uint4(wh[4],wh[5],wh[6],wh[7]);
            *(uint4*)&Bl[bkp][bn8]     = make_uint4(wl[0],wl[1],wl[2],wl[3]);
            *(uint4*)&Bl[bkp][bn8 + 4] = make_uint4(wl[4],wl[5],wl[6],wl[7]);
        }
        __syncthreads();

        // ---- MMAs: 2 k-steps of 16 ----
        #pragma unroll
        for (int ks = 0; ks < 2; ++ks) {
            // A frags (PTX m16n8k16.row layout):
            // r0=(m=g, k=2tig,2tig+1) r1=(m=g+8, same) r2=(m=g, k+8) r3=(m=g+8, k+8)
            uint32_t ah[2][4], al[2][4];
            #pragma unroll
            for (int mf = 0; mf < 2; ++mf) {
                const int mb = wm * 32 + mf * 16;
                const int kc = ks * 16 + 2 * tig;
                ah[mf][0] = *(const uint32_t*)&Ah[mb + g    ][kc    ];
                ah[mf][1] = *(const uint32_t*)&Ah[mb + g + 8][kc    ];
                ah[mf][2] = *(const uint32_t*)&Ah[mb + g    ][kc + 8];
                ah[mf][3] = *(const uint32_t*)&Ah[mb + g + 8][kc + 8];
                al[mf][0] = *(const uint32_t*)&Al[mb + g    ][kc    ];
                al[mf][1] = *(const uint32_t*)&Al[mb + g + 8][kc    ];
                al[mf][2] = *(const uint32_t*)&Al[mb + g    ][kc + 8];
                al[mf][3] = *(const uint32_t*)&Al[mb + g + 8][kc + 8];
            }
            #pragma unroll
            for (int ng = 0; ng < 8; ++ng) {
                // B frags (col layout): b0=(k=2tig..,n=g), b1=(k=2tig+8..,n=g)
                const int nn = wn * 64 + ng * 8 + g;
                const uint32_t bh0 = Bh[ks*8 + tig    ][nn];
                const uint32_t bh1 = Bh[ks*8 + tig + 4][nn];
                const uint32_t bl0 = Bl[ks*8 + tig    ][nn];
                const uint32_t bl1 = Bl[ks*8 + tig + 4][nn];
                #pragma unroll
                for (int mf = 0; mf < 2; ++mf) {
                    mma_bf16(acc[mf][ng], ah[mf], bh0, bh1);   // hi*hi
                    mma_bf16(acc[mf][ng], al[mf], bh0, bh1);   // lo*hi
                    mma_bf16(acc[mf][ng], ah[mf], bl0, bl1);   // hi*lo
                }
            }
        }
    }

    // ---- epilogue: c0,c1 at (row g, cols 2tig..); c2,c3 at (row g+8) ----
    #pragma unroll
    for (int mf = 0; mf < 2; ++mf) {
        const int rbase = m0 + wm * 32 + mf * 16;
        #pragma unroll
        for (int half = 0; half < 2; ++half) {
            const int r = rbase + g + half * 8;
            if (r < cnt) {
                float* orow = Out + (size_t)(off + r) * NTOT + n0;
                const float* brow = bias + (size_t)e * NTOT + n0;
                #pragma unroll
                for (int ng = 0; ng < 8; ++ng) {
                    const int c = wn * 64 + ng * 8 + tig * 2;
                    float v0 = acc[mf][ng][half * 2 + 0] + brow[c];
                    float v1 = acc[mf][ng][half * 2 + 1] + brow[c + 1];
                    if (DOGELU) { v0 = gelu_exact(v0); v1 = gelu_exact(v1); }
                    orow[c]     = v0;
                    orow[c + 1] = v1;
                }
            }
        }
    }
}

// ---------------- combine ----------------
__global__ void combine_kernel(float* __restrict__ out) {
    const int t = blockIdx.x;
    const int tid = threadIdx.x;
    __shared__ float w[TOPK];
    __shared__ int   s[TOPK];
    if (tid < TOPK) { w[tid] = g_weight[t * TOPK + tid]; s[tid] = g_token_slot[t * TOPK + tid]; }
    __syncthreads();
    const float* y0 = g_Y + (size_t)s[0] * DIM;
    const float* y1 = g_Y + (size_t)s[1] * DIM;
    const float* y2 = g_Y + (size_t)s[2] * DIM;
    const float* y3 = g_Y + (size_t)s[3] * DIM;
    float* o = out + (size_t)t * DIM;
    for (int h = tid; h < DIM; h += 256)
        o[h] = w[0]*y0[h] + w[1]*y1[h] + w[2]*y2[h] + w[3]*y3[h];
}

// ---------------- aux scalar ----------------
__global__ void aux_kernel(const float* __restrict__ load_ema, float* __restrict__ aux_out) {
    int e = threadIdx.x;  // 32
    float frac = ((float)g_count[e] / (float)NTOK) / (float)TOPK;
    float pm   = g_probs_sum[e] / (float)NTOK;
    float contrib = frac * pm;
    float ema = load_ema[e];
    float csum = contrib, esum = ema;
    #pragma unroll
    for (int o = 16; o > 0; o >>= 1) {
        csum += __shfl_xor_sync(0xffffffff, csum, o);
        esum += __shfl_xor_sync(0xffffffff, esum, o);
    }
    float lp = ema / (esum + 1e-8f);
    float entropy = -lp * logf(lp + 1e-8f);
    #pragma unroll
    for (int o = 16; o > 0; o >>= 1)
        entropy += __shfl_xor_sync(0xffffffff, entropy, o);
    if (e == 0) {
        float base_aux = (float)NEXP * csum;
        float reg = logf((float)NEXP) - entropy;
        aux_out[0] = base_aux + 0.001f * reg;
    }
}

// ---------------- launch ----------------
extern "C" void kernel_launch(void* const* d_in, const int* in_sizes, int n_in,
                              void* d_out, int out_size) {
    const float* x   = (const float*)d_in[0];
    const float* gw  = (const float*)d_in[1];
    const float* gb  = (const float*)d_in[2];
    const float* w1  = (const float*)d_in[3];
    const float* b1  = (const float*)d_in[4];
    const float* w2  = (const float*)d_in[5];
    const float* b2  = (const float*)d_in[6];
    const float* ema = (const float*)d_in[7];
    float* out = (float*)d_out;

    init_kernel<<<1, 64>>>();
    router_kernel<<<NTOK, 128>>>(x, gw, gb);
    offsets_kernel<<<1, 1024>>>();

    // GEMM1: g_H = GELU(X_gathered @ W1 + b1)
    moe_gemm<DIM, FFN, true, true, false, true>
        <<<dim3(FFN / TN, NTOK / TM, NEXP), 256>>>(x, w1, b1);
    // GEMM2: g_Y = g_H @ W2 + b2
    moe_gemm<FFN, DIM, false, false, true, false>
        <<<dim3(DIM / TN, NTOK / TM, NEXP), 256>>>(x, w2, b2);

    combine_kernel<<<NTOK, 256>>>(out);
    if (out_size > NTOK * DIM) {
        aux_kernel<<<1, 32>>>(ema, out + (size_t)NTOK * DIM);
    }
}